// round 15
// baseline (speedup 1.0000x reference)
#include <cuda_runtime.h>
#include <cuda_bf16.h>
#include <math.h>

// ---------------- problem constants ----------------
constexpr int kN  = 2048;
constexpr int kC  = 256;
constexpr int kCO = 128;
constexpr int kM  = 8 * kN;      // 16384
constexpr int kG  = 66;
constexpr int kG3 = kG * kG * kG;
constexpr int kZROW = 2 * kN;    // zero-pad row index in g_hhi/g_hlo

// ---------------- scratch globals (NEVER passed as kernel args from host) ----
__device__ __nv_bfloat16 g_hhi [(2 * kN + 1) * kC];
__device__ __nv_bfloat16 g_hlo [(2 * kN + 1) * kC];
__device__ __nv_bfloat16 g_h1hi[(kM + 1) * kCO];
__device__ __nv_bfloat16 g_h1lo[(kM + 1) * kCO];
__device__ float g_h1acc[(kM + kN) * kCO];   // [kM,kM+kN) = skip accumulator
__device__ int   g_grid[kG3];
__device__ int   g_nidx [kM * 27];
__device__ int   g_nidx1[kM * 27];
__device__ int   g_mask[kM];
__device__ int   g_cnt;
__device__ int   g_list[kM];
__device__ int   g_in1 [kM * 27 + 28 * 128 + 2048], g_out1[kM * 27 + 28 * 128 + 2048];
__device__ int   g_in2 [kM * 27 + 27 * 128], g_out2[kM * 27 + 27 * 128];
__device__ int   g_cnt1[28], g_start1[28], g_plen1[28];
__device__ int   g_cnt2[27], g_start2[27], g_plen2[27];
__device__ __nv_bfloat16 g_w1hi[28 * 128 * kC],  g_w1lo[28 * 128 * kC];
__device__ __nv_bfloat16 g_w2hi[27 * 128 * kCO], g_w2lo[27 * 128 * kCO];

// ---------------- ptx helpers ----------------
__device__ __forceinline__ unsigned smem_u32(const void* p) {
    unsigned a;
    asm("{ .reg .u64 t; cvta.to.shared.u64 t, %1; cvt.u32.u64 %0, t; }"
        : "=r"(a) : "l"(p));
    return a;
}
__device__ __forceinline__ void ldsm4(unsigned* r, unsigned addr) {
    asm volatile("ldmatrix.sync.aligned.m8n8.x4.shared.b16 {%0,%1,%2,%3}, [%4];"
                 : "=r"(r[0]), "=r"(r[1]), "=r"(r[2]), "=r"(r[3]) : "r"(addr));
}
__device__ __forceinline__ void mma16816(float* d, const unsigned* a,
                                         const unsigned* b) {
    asm volatile(
        "mma.sync.aligned.m16n8k16.row.col.f32.bf16.bf16.f32 "
        "{%0,%1,%2,%3}, {%4,%5,%6,%7}, {%8,%9}, {%0,%1,%2,%3};"
        : "+f"(d[0]), "+f"(d[1]), "+f"(d[2]), "+f"(d[3])
        : "r"(a[0]), "r"(a[1]), "r"(a[2]), "r"(a[3]), "r"(b[0]), "r"(b[1]));
}
__device__ __forceinline__ void red_v4(float* p, float4 v) {
    asm volatile("red.global.add.v4.f32 [%0], {%1, %2, %3, %4};"
                 :: "l"(p), "f"(v.x), "f"(v.y), "f"(v.z), "f"(v.w) : "memory");
}

// ---------------- fused prep (scatter is a separate ordered launch) ----------
constexpr int PB0 = (kM * kCO) / 256;
constexpr int PBS = (kN * kCO) / 256;
constexpr int PT1 = 27 * 8 * 4;
constexpr int PTS = 8 * 4;
constexpr int PT2 = 27 * 4 * 4;
constexpr int PB3 = (kG3 + 255) / 256;
constexpr int PREP_BLOCKS = PB0 + PBS + PT1 + PTS + PT2 + PB3 + 1;

__global__ void prep_kernel(float* __restrict__ out,
                            const float* __restrict__ c1w,
                            const float* __restrict__ c2w,
                            const float* __restrict__ skw) {
    __shared__ float sT[32][33];
    const int b = blockIdx.x, t = threadIdx.x;
    if (b < PB0) {
        int i = b * 256 + t;
        g_h1acc[i] = 0.f;
        out[i] = 0.f;
    } else if (b < PB0 + PBS) {
        g_h1acc[kM * kCO + (b - PB0) * 256 + t] = 0.f;
    } else if (b < PB0 + PBS + PT1 + PTS) {
        int b1 = b - PB0 - PBS;
        int k = b1 >> 5, r = b1 & 31;
        int c0 = (r >> 2) * 32, n0 = (r & 3) * 32;
        const float* wk = (k < 27) ? (c1w + (size_t)k * kC * 128) : skw;
        int nx = t & 31, cy = t >> 5;
        #pragma unroll
        for (int i = 0; i < 4; ++i)
            sT[cy + 8 * i][nx] = wk[(size_t)(c0 + cy + 8 * i) * 128 + n0 + nx];
        __syncthreads();
        int cx = t & 31, ny = t >> 5;
        #pragma unroll
        for (int i = 0; i < 4; ++i) {
            float v = sT[cx][ny + 8 * i];
            __nv_bfloat16 h = __float2bfloat16(v);
            size_t o = (size_t)k * 128 * kC + (size_t)(n0 + ny + 8 * i) * kC + c0 + cx;
            g_w1hi[o] = h;
            g_w1lo[o] = __float2bfloat16(v - __bfloat162float(h));
        }
    } else if (b < PB0 + PBS + PT1 + PTS + PT2) {
        int b2 = b - PB0 - PBS - PT1 - PTS;
        int k = b2 >> 4, r = b2 & 15;
        int c0 = (r >> 2) * 32, n0 = (r & 3) * 32;
        const float* wk = c2w + (size_t)k * kCO * 128;
        int nx = t & 31, cy = t >> 5;
        #pragma unroll
        for (int i = 0; i < 4; ++i)
            sT[cy + 8 * i][nx] = wk[(size_t)(c0 + cy + 8 * i) * 128 + n0 + nx];
        __syncthreads();
        int cx = t & 31, ny = t >> 5;
        #pragma unroll
        for (int i = 0; i < 4; ++i) {
            float v = sT[cx][ny + 8 * i];
            __nv_bfloat16 h = __float2bfloat16(v);
            size_t o = (size_t)k * 128 * kCO + (size_t)(n0 + ny + 8 * i) * kCO + c0 + cx;
            g_w2hi[o] = h;
            g_w2lo[o] = __float2bfloat16(v - __bfloat162float(h));
        }
    } else if (b < PB0 + PBS + PT1 + PTS + PT2 + PB3) {
        int i = (b - PB0 - PBS - PT1 - PTS - PT2) * 256 + t;
        if (i < kG3) g_grid[i] = kM;
    } else {
        if (t < kC)  { g_hhi[(size_t)kZROW * kC + t] = __float2bfloat16(0.f);
                       g_hlo[(size_t)kZROW * kC + t] = __float2bfloat16(0.f); }
        if (t < kCO) { g_h1hi[kM * kCO + t] = __float2bfloat16(0.f);
                       g_h1lo[kM * kCO + t] = __float2bfloat16(0.f); }
        if (t == 0)  g_cnt = 0;
        if (t < 28)  { g_cnt1[t] = 0; if (t < 27) g_cnt2[t] = 0; }
    }
}

// ---------------- child scatter (separate launch: ordered AFTER sentinel) ----
__global__ void scatter_kernel(const int* __restrict__ coords) {
    int m = blockIdx.x * 256 + threadIdx.x;
    int n = m >> 3, j = m & 7;
    int cx = coords[n * 3 + 0] * 2 + ((j >> 2) & 1);
    int cy = coords[n * 3 + 1] * 2 + ((j >> 1) & 1);
    int cz = coords[n * 3 + 2] * 2 + (j & 1);
    g_grid[((cx + 1) * kG + (cy + 1)) * kG + (cz + 1)] = m;
}

// ---------------- per-parent: subdiv + mask + compact + LN + SiLU ------------
__global__ void row_kernel(const float* __restrict__ feats,
                           const float* __restrict__ n1w,
                           const float* __restrict__ n1b,
                           const float* __restrict__ sdw,
                           const float* __restrict__ sdb,
                           float* __restrict__ subdiv_out) {
    const int n = blockIdx.x;
    const int t = threadIdx.x;           // 256
    const int wid = t >> 5, lane = t & 31;
    __shared__ float sf[kC];
    __shared__ float red[8];
    __shared__ int   s_act[8];

    float x = feats[n * kC + t];
    sf[t] = x;
    {
        __nv_bfloat16 fh = __float2bfloat16(x);
        g_hhi[(size_t)(kN + n) * kC + t] = fh;
        g_hlo[(size_t)(kN + n) * kC + t] =
            __float2bfloat16(x - __bfloat162float(fh));
    }
    __syncthreads();

    {
        float p = 0.f;
        #pragma unroll
        for (int i = 0; i < 8; ++i) {
            int c = lane + i * 32;
            p += sf[c] * sdw[c * 8 + wid];
        }
        #pragma unroll
        for (int o = 16; o; o >>= 1) p += __shfl_xor_sync(0xffffffffu, p, o);
        if (lane == 0) {
            p += sdb[wid];
            subdiv_out[n * 8 + wid] = p;
            int act = (p > 0.f) ? 1 : 0;
            g_mask[n * 8 + wid] = act;
            s_act[wid] = act;
        }
    }

    float s = x;
    #pragma unroll
    for (int o = 16; o; o >>= 1) s += __shfl_xor_sync(0xffffffffu, s, o);
    if (lane == 0) red[wid] = s;
    __syncthreads();

    if (wid == 0) {
        bool act = (lane < 8) && (s_act[lane] != 0);
        unsigned ball = __ballot_sync(0xffffffffu, act);
        int c = __popc(ball);
        int base = 0;
        if (lane == 0 && c) base = atomicAdd(&g_cnt, c);
        base = __shfl_sync(0xffffffffu, base, 0);
        if (act) g_list[base + __popc(ball & ((1u << lane) - 1u))] = n * 8 + lane;
    }

    float tot = 0.f;
    #pragma unroll
    for (int i = 0; i < 8; ++i) tot += red[i];
    const float mean = tot * (1.f / kC);
    const float d = x - mean;
    float s2 = d * d;
    #pragma unroll
    for (int o = 16; o; o >>= 1) s2 += __shfl_xor_sync(0xffffffffu, s2, o);
    __syncthreads();
    if (lane == 0) red[wid] = s2;
    __syncthreads();
    float vtot = 0.f;
    #pragma unroll
    for (int i = 0; i < 8; ++i) vtot += red[i];
    const float var = vtot * (1.f / kC);
    const float y = d * rsqrtf(var + 1e-6f) * n1w[t] + n1b[t];
    const float h = y / (1.f + expf(-y));
    __nv_bfloat16 hh = __float2bfloat16(h);
    g_hhi[(size_t)n * kC + t] = hh;
    g_hlo[(size_t)n * kC + t] = __float2bfloat16(h - __bfloat162float(hh));
}

// ---------------- neighbor table + tap counting: ONE tap per block -----------
__global__ void nidx_kernel(const int* __restrict__ coords) {
    __shared__ int c1s, c2s;
    const int t = threadIdx.x;
    const int lane = t & 31;
    const int k = blockIdx.y;            // 0..26
    if (t == 0) { c1s = 0; c2s = 0; }
    __syncthreads();

    int m = blockIdx.x * 256 + t;
    int n = m >> 3, j = m & 7;
    int gx = coords[n * 3 + 0] * 2 + ((j >> 2) & 1) + 1;
    int gy = coords[n * 3 + 1] * 2 + ((j >> 1) & 1) + 1;
    int gz = coords[n * 3 + 2] * 2 + (j & 1) + 1;
    const int msk = g_mask[m];
    int dx = k / 9 - 1, dy = (k / 3) % 3 - 1, dz = k % 3 - 1;
    int nb = g_grid[((gx + dx) * kG + (gy + dy)) * kG + (gz + dz)];
    g_nidx[m * 27 + k] = nb;
    int in1 = (nb == kM) ? kZROW : (g_mask[nb] ? (nb >> 3) : kZROW);
    g_nidx1[m * 27 + k] = in1;
    unsigned b1 = __ballot_sync(0xffffffffu, in1 != kZROW);
    unsigned b2 = __ballot_sync(0xffffffffu, msk && (nb != kM));
    if (lane == 0) {
        if (b1) atomicAdd(&c1s, __popc(b1));
        if (b2) atomicAdd(&c2s, __popc(b2));
    }
    __syncthreads();
    if (t == 0) {
        if (c1s) atomicAdd(&g_cnt1[k], c1s);
        if (c2s) atomicAdd(&g_cnt2[k], c2s);
    }
}

// ---------------- scan: starts + padded lengths (+ dense skip segment 27) ----
__global__ void tap_scan_kernel() {
    if (threadIdx.x != 0) return;
    int s1 = 0, s2 = 0;
    for (int k = 0; k < 27; ++k) {
        int c = g_cnt1[k], p = (c + 127) & ~127;
        g_start1[k] = s1; g_plen1[k] = p; s1 += p;
        c = g_cnt2[k]; p = (c + 127) & ~127;
        g_start2[k] = s2; g_plen2[k] = p; s2 += p;
    }
    g_start1[27] = s1; g_plen1[27] = kN;
}

// ---------------- fill pair lists (55 blocks) ----------------
__device__ __forceinline__ bool tap_flag_rt(int mode, int m, int k, int& in_id) {
    if (mode == 1) {
        in_id = g_nidx1[m * 27 + k];
        return in_id != kZROW;
    } else {
        in_id = g_nidx[m * 27 + k];
        return g_mask[m] && (in_id != kM);
    }
}

__global__ void tap_fill_kernel() {
    const int mode = (blockIdx.x < 28) ? 1 : 2;
    const int k = (mode == 1) ? blockIdx.x : (blockIdx.x - 28);
    const int t = threadIdx.x;
    int* __restrict__ pin  = (mode == 1) ? g_in1  : g_in2;
    int* __restrict__ pout = (mode == 1) ? g_out1 : g_out2;
    const int start = (mode == 1 ? g_start1 : g_start2)[k];

    if (mode == 1 && k == 27) {
        for (int i = t; i < kN; i += 256) {
            pin[start + i] = kN + i;
            pout[start + i] = kM + i;
        }
        return;
    }

    int cnt = 0;
    #pragma unroll 4
    for (int r = 0; r < 64; ++r) {
        int in_id;
        if (tap_flag_rt(mode, t * 64 + r, k, in_id)) ++cnt;
    }
    __shared__ int sh[256];
    sh[t] = cnt;
    __syncthreads();
    #pragma unroll
    for (int off = 1; off < 256; off <<= 1) {
        int u = (t >= off) ? sh[t - off] : 0;
        __syncthreads();
        sh[t] += u;
        __syncthreads();
    }
    int w = start + sh[t] - cnt;
    const int tot = sh[255];
    for (int r = 0; r < 64; ++r) {
        int m = t * 64 + r, in_id;
        if (tap_flag_rt(mode, m, k, in_id)) {
            pin[w] = in_id;
            pout[w] = m;
            ++w;
        }
    }
    const int plen = (mode == 1 ? g_plen1 : g_plen2)[k];
    for (int i = tot + t; i < plen; i += 256) {
        pin[start + i] = (mode == 1) ? kZROW : kM;
        pout[start + i] = -1;
    }
}

// ---------------- tensor-core tap GEMM: double-buffered smem -----------------
// Block tile M=128 x N=128, BK=32, 256 threads (8 warps as 4x2, warp 32x64).
// Dynamic smem: 2 buffers x (Ahi|Alo|Bhi|Blo each 10240B) = 81920B.
// ONE __syncthreads per chunk: store next chunk to other buffer during compute.
constexpr int kBUF = 40960;
constexpr int SMEM_TAP = 2 * kBUF;

template <int MODE>
__global__ void __launch_bounds__(256)
tapgemm_mma(float* __restrict__ ext_out)
{
    constexpr int CIN = (MODE == 1) ? kC : kCO;
    constexpr int BK  = 32;
    constexpr int NCH = CIN / BK;
    constexpr int LDB = 80;

    extern __shared__ __align__(16) char smem_raw[];
    __shared__ int sIdx[128], sOut[128];
    float* T = (float*)smem_raw;            // epilogue alias (64x132 floats)

    const int k = blockIdx.x >> 7;
    const int s = blockIdx.x & 127;
    const int plen = (MODE == 1 ? g_plen1 : g_plen2)[k];
    if (s * 128 >= plen) return;
    const int base = (MODE == 1 ? g_start1 : g_start2)[k] + s * 128;

    const __nv_bfloat16* __restrict__ shi = (MODE == 1) ? g_hhi : g_h1hi;
    const __nv_bfloat16* __restrict__ slo = (MODE == 1) ? g_hlo : g_h1lo;
    const __nv_bfloat16* __restrict__ whi = (MODE == 1) ? g_w1hi : g_w2hi;
    const __nv_bfloat16* __restrict__ wlo = (MODE == 1) ? g_w1lo : g_w2lo;
    const int* __restrict__ pin  = (MODE == 1) ? g_in1  : g_in2;
    const int* __restrict__ pout = (MODE == 1) ? g_out1 : g_out2;
    float* __restrict__ dstbase  = (MODE == 1) ? g_h1acc : ext_out;

    const int t = threadIdx.x;
    if (t < 128) {
        sIdx[t] = pin[base + t];
        sOut[t] = pout[base + t];
    }
    __syncthreads();

    const unsigned uB0 = smem_u32(smem_raw);

    const int warp = t >> 5, lane = t & 31;
    const int g = lane >> 2, tid = lane & 3;
    const int wm = (warp & 3) * 32;
    const int wn = (warp >> 2) * 64;

    const int a_row  = lane & 15;
    const int a_koff = (lane >> 4) * 16;
    const int b_row  = (lane & 7) + (lane >> 4) * 8;
    const int b_koff = ((lane >> 3) & 1) * 16;

    float acc[2][8][4];
    #pragma unroll
    for (int i = 0; i < 2; ++i)
        #pragma unroll
        for (int j = 0; j < 8; ++j)
            #pragma unroll
            for (int q = 0; q < 4; ++q) acc[i][j][q] = 0.f;

    const size_t wko = (size_t)k * 128 * CIN;

    const int r0 = t >> 2, j0 = t & 3;
    const int r1 = 64 + r0;
    const size_t a0b = (size_t)sIdx[r0] * CIN;
    const size_t a1b = (size_t)sIdx[r1] * CIN;
    const size_t b0b = wko + (size_t)r0 * CIN;
    const size_t b1b = wko + (size_t)r1 * CIN;
    const int to0 = r0 * LDB + j0 * 16;
    const int to1 = r1 * LDB + j0 * 16;

    // prefetch chunks 0 and 1 into register slots
    uint4 P[2][8];
    #pragma unroll
    for (int sl = 0; sl < 2 && sl < NCH; ++sl) {
        const int c0 = sl * BK;
        P[sl][0] = *((const uint4*)(shi + a0b + c0) + j0);
        P[sl][1] = *((const uint4*)(slo + a0b + c0) + j0);
        P[sl][2] = *((const uint4*)(whi + b0b + c0) + j0);
        P[sl][3] = *((const uint4*)(wlo + b0b + c0) + j0);
        P[sl][4] = *((const uint4*)(shi + a1b + c0) + j0);
        P[sl][5] = *((const uint4*)(slo + a1b + c0) + j0);
        P[sl][6] = *((const uint4*)(whi + b1b + c0) + j0);
        P[sl][7] = *((const uint4*)(wlo + b1b + c0) + j0);
    }

    // pre-store chunk 0 into buffer 0
    {
        char* d = smem_raw;
        *(uint4*)(d + to0)         = P[0][0];
        *(uint4*)(d + 10240 + to0) = P[0][1];
        *(uint4*)(d + 20480 + to0) = P[0][2];
        *(uint4*)(d + 30720 + to0) = P[0][3];
        *(uint4*)(d + to1)         = P[0][4];
        *(uint4*)(d + 10240 + to1) = P[0][5];
        *(uint4*)(d + 20480 + to1) = P[0][6];
        *(uint4*)(d + 30720 + to1) = P[0][7];
    }
    __syncthreads();

    #pragma unroll
    for (int ch = 0; ch < NCH; ++ch) {
        // store chunk ch+1 (prefetched) into the OTHER buffer
        if (ch + 1 < NCH) {
            const int nsl = (ch + 1) & 1;
            char* d = smem_raw + nsl * kBUF;
            *(uint4*)(d + to0)         = P[nsl][0];
            *(uint4*)(d + 10240 + to0) = P[nsl][1];
            *(uint4*)(d + 20480 + to0) = P[nsl][2];
            *(uint4*)(d + 30720 + to0) = P[nsl][3];
            *(uint4*)(d + to1)         = P[nsl][4];
            *(uint4*)(d + 10240 + to1) = P[nsl][5];
            *(uint4*)(d + 20480 + to1) = P[nsl][6];
            *(uint4*)(d + 30720 + to1) = P[nsl][7];
        }
        // prefetch chunk ch+2 into slot (ch&1) — chunk ch is already staged
        if (ch + 2 < NCH) {
            const int sl = ch & 1;
            const int c0 = (ch + 2) * BK;
            P[sl][0] = *((const uint4*)(shi + a0b + c0) + j0);
            P[sl][1] = *((const uint4*)(slo + a0b + c0) + j0);
            P[sl][2] = *((const uint4*)(whi + b0b + c0) + j0);
            P[sl][3] = *((const uint4*)(wlo + b0b + c0) + j0);
            P[sl][4] = *((const uint4*)(shi + a1b + c0) + j0);
            P[sl][5] = *((const uint4*)(slo + a1b + c0) + j0);
            P[sl][6] = *((const uint4*)(whi + b1b + c0) + j0);
            P[sl][7] = *((const uint4*)(wlo + b1b + c0) + j0);
        }

        // compute chunk ch from buffer (ch&1)
        const unsigned bb = uB0 + (unsigned)((ch & 1) * kBUF);
        const unsigned uAhi = bb, uAlo = bb + 10240;
        const unsigned uBhi = bb + 20480, uBlo = bb + 30720;
        #pragma unroll
        for (int ks = 0; ks < BK / 16; ++ks) {
            const int akb = ks * 32 + a_koff;
            const int bkb = ks * 32 + b_koff;
            unsigned ah[2][4], al[2][4];
            #pragma unroll
            for (int mt = 0; mt < 2; ++mt) {
                unsigned aoff = (unsigned)((wm + mt * 16 + a_row) * LDB + akb);
                ldsm4(ah[mt], uAhi + aoff);
                ldsm4(al[mt], uAlo + aoff);
            }
            #pragma unroll
            for (int n2 = 0; n2 < 4; ++n2) {
                unsigned boff = (unsigned)((wn + n2 * 16 + b_row) * LDB + bkb);
                unsigned bh[4], bl[4];
                ldsm4(bh, uBhi + boff);
                ldsm4(bl, uBlo + boff);
                #pragma unroll
                for (int mt = 0; mt < 2; ++mt) {
                    mma16816(acc[mt][n2 * 2],     ah[mt], bh);
                    mma16816(acc[mt][n2 * 2],     ah[mt], bl);
                    mma16816(acc[mt][n2 * 2],     al[mt], bh);
                    mma16816(acc[mt][n2 * 2 + 1], ah[mt], bh + 2);
                    mma16816(acc[mt][n2 * 2 + 1], ah[mt], bl + 2);
                    mma16816(acc[mt][n2 * 2 + 1], al[mt], bh + 2);
                }
            }
        }
        __syncthreads();     // chunk ch+1 stores visible; buffer ch&1 reusable
    }

    // ---- epilogue: smem transpose (aliases buffer 0) -> red.v4 scatter ----
    const int myp = (warp & 3) >> 1;
    const int cq = tid * 2;
    #pragma unroll
    for (int p = 0; p < 2; ++p) {
        if (myp == p) {
            #pragma unroll
            for (int mt = 0; mt < 2; ++mt)
                #pragma unroll
                for (int half = 0; half < 2; ++half) {
                    int lrow = (wm & 63) + mt * 16 + g + half * 8;
                    #pragma unroll
                    for (int na = 0; na < 8; ++na) {
                        int col = wn + na * 8 + cq;
                        *(float2*)&T[lrow * 132 + col] =
                            make_float2(acc[mt][na][half * 2],
                                        acc[mt][na][half * 2 + 1]);
                    }
                }
        }
        __syncthreads();
        #pragma unroll
        for (int i = 0; i < 8; ++i) {
            int lrow = i * 8 + warp;
            int cpos = lane * 4;
            int orow = sOut[p * 64 + lrow];
            if (orow >= 0) {
                float4 v = *(const float4*)&T[lrow * 132 + cpos];
                red_v4(dstbase + (size_t)orow * kCO + cpos, v);
            }
        }
        __syncthreads();
    }
}

// ---------------- h1 epilogue: 2 rows per 256-thread block -------------------
__global__ void h1_ep_kernel(const float* __restrict__ c1b) {
    const int t = threadIdx.x;
    const int r = t >> 7;                   // 0/1: row within block
    const int m = blockIdx.x * 2 + r;
    const int ct = t & 127;
    const int wid = (t >> 5) & 3, lane = t & 31;
    __shared__ float red[2][4];
    float x = g_h1acc[(size_t)m * kCO + ct] + c1b[ct];
    float s = x;
    #pragma unroll
    for (int o = 16; o; o >>= 1) s += __shfl_xor_sync(0xffffffffu, s, o);
    if (lane == 0) red[r][wid] = s;
    __syncthreads();
    const float mean = (red[r][0] + red[r][1] + red[r][2] + red[r][3]) * (1.f / kCO);
    const float d = x - mean;
    float s2 = d * d;
    #pragma unroll
    for (int o = 16; o; o >>= 1) s2 += __shfl_xor_sync(0xffffffffu, s2, o);
    __syncthreads();
    if (lane == 0) red[r][wid] = s2;
    __syncthreads();
    const float var = (red[r][0] + red[r][1] + red[r][2] + red[r][3]) * (1.f / kCO);
    const float y = d * rsqrtf(var + 1e-6f);
    const float h = y / (1.f + expf(-y));
    __nv_bfloat16 hh = __float2bfloat16(h);
    g_h1hi[(size_t)m * kCO + ct] = hh;
    g_h1lo[(size_t)m * kCO + ct] = __float2bfloat16(h - __bfloat162float(hh));
}

// ---------------- out epilogue: += c2 bias + skip acc + skip bias ------------
__global__ void out_ep_kernel(float* __restrict__ out,
                              const float* __restrict__ c2b,
                              const float* __restrict__ skb) {
    if ((int)blockIdx.x >= g_cnt) return;
    const int m = g_list[blockIdx.x], t = threadIdx.x;   // 128
    out[(size_t)m * kCO + t] +=
        c2b[t] + skb[t] + g_h1acc[(size_t)(kM + (m >> 3)) * kCO + t];
}

// ---------------- launch (ONLY harness pointers cross the boundary) ----------
extern "C" void kernel_launch(void* const* d_in, const int* in_sizes, int n_in,
                              void* d_out, int out_size)
{
    const float* feats = (const float*)d_in[0];
    const float* n1w   = (const float*)d_in[1];
    const float* n1b   = (const float*)d_in[2];
    const float* sdw   = (const float*)d_in[3];
    const float* sdb   = (const float*)d_in[4];
    const float* c1w   = (const float*)d_in[5];
    const float* c1b   = (const float*)d_in[6];
    const float* c2w   = (const float*)d_in[7];
    const float* c2b   = (const float*)d_in[8];
    const float* skw   = (const float*)d_in[9];
    const float* skb   = (const float*)d_in[10];
    const int*   coords= (const int*)d_in[11];

    float* out        = (float*)d_out;
    float* subdiv_out = out + (size_t)kM * kCO;

    static bool attr_done = false;
    if (!attr_done) {
        cudaFuncSetAttribute(tapgemm_mma<1>,
            cudaFuncAttributeMaxDynamicSharedMemorySize, SMEM_TAP);
        cudaFuncSetAttribute(tapgemm_mma<2>,
            cudaFuncAttributeMaxDynamicSharedMemorySize, SMEM_TAP);
        attr_done = true;
    }

    prep_kernel<<<PREP_BLOCKS, 256>>>(out, c1w, c2w, skw);
    scatter_kernel<<<kM / 256, 256>>>(coords);        // MUST follow sentinel fill
    row_kernel<<<kN, 256>>>(feats, n1w, n1b, sdw, sdb, subdiv_out);
    nidx_kernel<<<dim3(kM / 256, 27), 256>>>(coords);
    tap_scan_kernel<<<1, 32>>>();
    tap_fill_kernel<<<55, 256>>>();
    tapgemm_mma<1><<<28 * 128, 256, SMEM_TAP>>>(nullptr);
    h1_ep_kernel<<<kM / 2, 256>>>(c1b);
    tapgemm_mma<2><<<27 * 128, 256, SMEM_TAP>>>(out);
    out_ep_kernel<<<kM, 128>>>(out, c2b, skb);
}

// round 16
// speedup vs baseline: 1.0076x; 1.0076x over previous
#include <cuda_runtime.h>
#include <cuda_bf16.h>
#include <math.h>

// ---------------- problem constants ----------------
constexpr int kN  = 2048;
constexpr int kC  = 256;
constexpr int kCO = 128;
constexpr int kM  = 8 * kN;      // 16384
constexpr int kG  = 66;
constexpr int kG3 = kG * kG * kG;
constexpr int kZROW = 2 * kN;    // zero-pad row index in g_hhi/g_hlo

// ---------------- scratch globals (NEVER passed as kernel args from host) ----
__device__ __nv_bfloat16 g_hhi [(2 * kN + 1) * kC];
__device__ __nv_bfloat16 g_hlo [(2 * kN + 1) * kC];
__device__ __nv_bfloat16 g_h1hi[(kM + 1) * kCO];
__device__ __nv_bfloat16 g_h1lo[(kM + 1) * kCO];
__device__ float g_h1acc[(kM + kN) * kCO];   // [kM,kM+kN) = skip accumulator
__device__ int   g_grid[kG3];
__device__ int   g_nidx [kM * 27];
__device__ int   g_nidx1[kM * 27];
__device__ int   g_mask[kM];
__device__ int   g_cnt;
__device__ int   g_list[kM];
__device__ int   g_in1 [kM * 27 + 28 * 128 + 2048], g_out1[kM * 27 + 28 * 128 + 2048];
__device__ int   g_in2 [kM * 27 + 27 * 128], g_out2[kM * 27 + 27 * 128];
__device__ int   g_cnt1[28], g_start1[28], g_plen1[28];
__device__ int   g_cnt2[27], g_start2[27], g_plen2[27];
__device__ __nv_bfloat16 g_w1hi[28 * 128 * kC],  g_w1lo[28 * 128 * kC];
__device__ __nv_bfloat16 g_w2hi[27 * 128 * kCO], g_w2lo[27 * 128 * kCO];

// ---------------- ptx helpers ----------------
__device__ __forceinline__ unsigned smem_u32(const void* p) {
    unsigned a;
    asm("{ .reg .u64 t; cvta.to.shared.u64 t, %1; cvt.u32.u64 %0, t; }"
        : "=r"(a) : "l"(p));
    return a;
}
__device__ __forceinline__ void ldsm4(unsigned* r, unsigned addr) {
    asm volatile("ldmatrix.sync.aligned.m8n8.x4.shared.b16 {%0,%1,%2,%3}, [%4];"
                 : "=r"(r[0]), "=r"(r[1]), "=r"(r[2]), "=r"(r[3]) : "r"(addr));
}
__device__ __forceinline__ void mma16816(float* d, const unsigned* a,
                                         const unsigned* b) {
    asm volatile(
        "mma.sync.aligned.m16n8k16.row.col.f32.bf16.bf16.f32 "
        "{%0,%1,%2,%3}, {%4,%5,%6,%7}, {%8,%9}, {%0,%1,%2,%3};"
        : "+f"(d[0]), "+f"(d[1]), "+f"(d[2]), "+f"(d[3])
        : "r"(a[0]), "r"(a[1]), "r"(a[2]), "r"(a[3]), "r"(b[0]), "r"(b[1]));
}
__device__ __forceinline__ void red_v4(float* p, float4 v) {
    asm volatile("red.global.add.v4.f32 [%0], {%1, %2, %3, %4};"
                 :: "l"(p), "f"(v.x), "f"(v.y), "f"(v.z), "f"(v.w) : "memory");
}

// ---------------- fused prep (scatter is a separate ordered launch) ----------
constexpr int PB0 = (kM * kCO) / 256;
constexpr int PBS = (kN * kCO) / 256;
constexpr int PT1 = 27 * 8 * 4;
constexpr int PTS = 8 * 4;
constexpr int PT2 = 27 * 4 * 4;
constexpr int PB3 = (kG3 + 255) / 256;
constexpr int PREP_BLOCKS = PB0 + PBS + PT1 + PTS + PT2 + PB3 + 1;

__global__ void prep_kernel(float* __restrict__ out,
                            const float* __restrict__ c1w,
                            const float* __restrict__ c2w,
                            const float* __restrict__ skw) {
    __shared__ float sT[32][33];
    const int b = blockIdx.x, t = threadIdx.x;
    if (b < PB0) {
        int i = b * 256 + t;
        g_h1acc[i] = 0.f;
        out[i] = 0.f;
    } else if (b < PB0 + PBS) {
        g_h1acc[kM * kCO + (b - PB0) * 256 + t] = 0.f;
    } else if (b < PB0 + PBS + PT1 + PTS) {
        int b1 = b - PB0 - PBS;
        int k = b1 >> 5, r = b1 & 31;
        int c0 = (r >> 2) * 32, n0 = (r & 3) * 32;
        const float* wk = (k < 27) ? (c1w + (size_t)k * kC * 128) : skw;
        int nx = t & 31, cy = t >> 5;
        #pragma unroll
        for (int i = 0; i < 4; ++i)
            sT[cy + 8 * i][nx] = wk[(size_t)(c0 + cy + 8 * i) * 128 + n0 + nx];
        __syncthreads();
        int cx = t & 31, ny = t >> 5;
        #pragma unroll
        for (int i = 0; i < 4; ++i) {
            float v = sT[cx][ny + 8 * i];
            __nv_bfloat16 h = __float2bfloat16(v);
            size_t o = (size_t)k * 128 * kC + (size_t)(n0 + ny + 8 * i) * kC + c0 + cx;
            g_w1hi[o] = h;
            g_w1lo[o] = __float2bfloat16(v - __bfloat162float(h));
        }
    } else if (b < PB0 + PBS + PT1 + PTS + PT2) {
        int b2 = b - PB0 - PBS - PT1 - PTS;
        int k = b2 >> 4, r = b2 & 15;
        int c0 = (r >> 2) * 32, n0 = (r & 3) * 32;
        const float* wk = c2w + (size_t)k * kCO * 128;
        int nx = t & 31, cy = t >> 5;
        #pragma unroll
        for (int i = 0; i < 4; ++i)
            sT[cy + 8 * i][nx] = wk[(size_t)(c0 + cy + 8 * i) * 128 + n0 + nx];
        __syncthreads();
        int cx = t & 31, ny = t >> 5;
        #pragma unroll
        for (int i = 0; i < 4; ++i) {
            float v = sT[cx][ny + 8 * i];
            __nv_bfloat16 h = __float2bfloat16(v);
            size_t o = (size_t)k * 128 * kCO + (size_t)(n0 + ny + 8 * i) * kCO + c0 + cx;
            g_w2hi[o] = h;
            g_w2lo[o] = __float2bfloat16(v - __bfloat162float(h));
        }
    } else if (b < PB0 + PBS + PT1 + PTS + PT2 + PB3) {
        int i = (b - PB0 - PBS - PT1 - PTS - PT2) * 256 + t;
        if (i < kG3) g_grid[i] = kM;
    } else {
        if (t < kC)  { g_hhi[(size_t)kZROW * kC + t] = __float2bfloat16(0.f);
                       g_hlo[(size_t)kZROW * kC + t] = __float2bfloat16(0.f); }
        if (t < kCO) { g_h1hi[kM * kCO + t] = __float2bfloat16(0.f);
                       g_h1lo[kM * kCO + t] = __float2bfloat16(0.f); }
        if (t == 0)  g_cnt = 0;
        if (t < 28)  { g_cnt1[t] = 0; if (t < 27) g_cnt2[t] = 0; }
    }
}

// ---------------- child scatter (separate launch: ordered AFTER sentinel) ----
__global__ void scatter_kernel(const int* __restrict__ coords) {
    int m = blockIdx.x * 256 + threadIdx.x;
    int n = m >> 3, j = m & 7;
    int cx = coords[n * 3 + 0] * 2 + ((j >> 2) & 1);
    int cy = coords[n * 3 + 1] * 2 + ((j >> 1) & 1);
    int cz = coords[n * 3 + 2] * 2 + (j & 1);
    g_grid[((cx + 1) * kG + (cy + 1)) * kG + (cz + 1)] = m;
}

// ---------------- per-parent: subdiv + mask + compact + LN + SiLU ------------
__global__ void row_kernel(const float* __restrict__ feats,
                           const float* __restrict__ n1w,
                           const float* __restrict__ n1b,
                           const float* __restrict__ sdw,
                           const float* __restrict__ sdb,
                           float* __restrict__ subdiv_out) {
    const int n = blockIdx.x;
    const int t = threadIdx.x;           // 256
    const int wid = t >> 5, lane = t & 31;
    __shared__ float sf[kC];
    __shared__ float red[8];
    __shared__ int   s_act[8];

    float x = feats[n * kC + t];
    sf[t] = x;
    {
        __nv_bfloat16 fh = __float2bfloat16(x);
        g_hhi[(size_t)(kN + n) * kC + t] = fh;
        g_hlo[(size_t)(kN + n) * kC + t] =
            __float2bfloat16(x - __bfloat162float(fh));
    }
    __syncthreads();

    {
        float p = 0.f;
        #pragma unroll
        for (int i = 0; i < 8; ++i) {
            int c = lane + i * 32;
            p += sf[c] * sdw[c * 8 + wid];
        }
        #pragma unroll
        for (int o = 16; o; o >>= 1) p += __shfl_xor_sync(0xffffffffu, p, o);
        if (lane == 0) {
            p += sdb[wid];
            subdiv_out[n * 8 + wid] = p;
            int act = (p > 0.f) ? 1 : 0;
            g_mask[n * 8 + wid] = act;
            s_act[wid] = act;
        }
    }

    float s = x;
    #pragma unroll
    for (int o = 16; o; o >>= 1) s += __shfl_xor_sync(0xffffffffu, s, o);
    if (lane == 0) red[wid] = s;
    __syncthreads();

    if (wid == 0) {
        bool act = (lane < 8) && (s_act[lane] != 0);
        unsigned ball = __ballot_sync(0xffffffffu, act);
        int c = __popc(ball);
        int base = 0;
        if (lane == 0 && c) base = atomicAdd(&g_cnt, c);
        base = __shfl_sync(0xffffffffu, base, 0);
        if (act) g_list[base + __popc(ball & ((1u << lane) - 1u))] = n * 8 + lane;
    }

    float tot = 0.f;
    #pragma unroll
    for (int i = 0; i < 8; ++i) tot += red[i];
    const float mean = tot * (1.f / kC);
    const float d = x - mean;
    float s2 = d * d;
    #pragma unroll
    for (int o = 16; o; o >>= 1) s2 += __shfl_xor_sync(0xffffffffu, s2, o);
    __syncthreads();
    if (lane == 0) red[wid] = s2;
    __syncthreads();
    float vtot = 0.f;
    #pragma unroll
    for (int i = 0; i < 8; ++i) vtot += red[i];
    const float var = vtot * (1.f / kC);
    const float y = d * rsqrtf(var + 1e-6f) * n1w[t] + n1b[t];
    const float h = y / (1.f + expf(-y));
    __nv_bfloat16 hh = __float2bfloat16(h);
    g_hhi[(size_t)n * kC + t] = hh;
    g_hlo[(size_t)n * kC + t] = __float2bfloat16(h - __bfloat162float(hh));
}

// ---------------- neighbor table + tap counting (64 x 9 blocks, 3 taps) ------
__global__ void nidx_kernel(const int* __restrict__ coords) {
    __shared__ int c1[3], c2[3];
    const int t = threadIdx.x;
    const int lane = t & 31;
    const int k0 = blockIdx.y * 3;
    if (t < 3) { c1[t] = 0; c2[t] = 0; }
    __syncthreads();

    int m = blockIdx.x * 256 + t;
    int n = m >> 3, j = m & 7;
    int gx = coords[n * 3 + 0] * 2 + ((j >> 2) & 1) + 1;
    int gy = coords[n * 3 + 1] * 2 + ((j >> 1) & 1) + 1;
    int gz = coords[n * 3 + 2] * 2 + (j & 1) + 1;
    const int msk = g_mask[m];
    #pragma unroll
    for (int kk = 0; kk < 3; ++kk) {
        int k = k0 + kk;
        int dx = k / 9 - 1, dy = (k / 3) % 3 - 1, dz = k % 3 - 1;
        int nb = g_grid[((gx + dx) * kG + (gy + dy)) * kG + (gz + dz)];
        g_nidx[m * 27 + k] = nb;
        int in1 = (nb == kM) ? kZROW : (g_mask[nb] ? (nb >> 3) : kZROW);
        g_nidx1[m * 27 + k] = in1;
        unsigned b1 = __ballot_sync(0xffffffffu, in1 != kZROW);
        unsigned b2 = __ballot_sync(0xffffffffu, msk && (nb != kM));
        if (lane == 0) {
            if (b1) atomicAdd(&c1[kk], __popc(b1));
            if (b2) atomicAdd(&c2[kk], __popc(b2));
        }
    }
    __syncthreads();
    if (t < 3) {
        if (c1[t]) atomicAdd(&g_cnt1[k0 + t], c1[t]);
        if (c2[t]) atomicAdd(&g_cnt2[k0 + t], c2[t]);
    }
}

// ---------------- scan: starts + padded lengths (+ dense skip segment 27) ----
__global__ void tap_scan_kernel() {
    if (threadIdx.x != 0) return;
    int s1 = 0, s2 = 0;
    for (int k = 0; k < 27; ++k) {
        int c = g_cnt1[k], p = (c + 127) & ~127;
        g_start1[k] = s1; g_plen1[k] = p; s1 += p;
        c = g_cnt2[k]; p = (c + 127) & ~127;
        g_start2[k] = s2; g_plen2[k] = p; s2 += p;
    }
    g_start1[27] = s1; g_plen1[27] = kN;
}

// ---------------- fill pair lists (55 blocks) ----------------
__device__ __forceinline__ bool tap_flag_rt(int mode, int m, int k, int& in_id) {
    if (mode == 1) {
        in_id = g_nidx1[m * 27 + k];
        return in_id != kZROW;
    } else {
        in_id = g_nidx[m * 27 + k];
        return g_mask[m] && (in_id != kM);
    }
}

__global__ void tap_fill_kernel() {
    const int mode = (blockIdx.x < 28) ? 1 : 2;
    const int k = (mode == 1) ? blockIdx.x : (blockIdx.x - 28);
    const int t = threadIdx.x;
    int* __restrict__ pin  = (mode == 1) ? g_in1  : g_in2;
    int* __restrict__ pout = (mode == 1) ? g_out1 : g_out2;
    const int start = (mode == 1 ? g_start1 : g_start2)[k];

    if (mode == 1 && k == 27) {
        for (int i = t; i < kN; i += 256) {
            pin[start + i] = kN + i;
            pout[start + i] = kM + i;
        }
        return;
    }

    int cnt = 0;
    #pragma unroll 4
    for (int r = 0; r < 64; ++r) {
        int in_id;
        if (tap_flag_rt(mode, t * 64 + r, k, in_id)) ++cnt;
    }
    __shared__ int sh[256];
    sh[t] = cnt;
    __syncthreads();
    #pragma unroll
    for (int off = 1; off < 256; off <<= 1) {
        int u = (t >= off) ? sh[t - off] : 0;
        __syncthreads();
        sh[t] += u;
        __syncthreads();
    }
    int w = start + sh[t] - cnt;
    const int tot = sh[255];
    for (int r = 0; r < 64; ++r) {
        int m = t * 64 + r, in_id;
        if (tap_flag_rt(mode, m, k, in_id)) {
            pin[w] = in_id;
            pout[w] = m;
            ++w;
        }
    }
    const int plen = (mode == 1 ? g_plen1 : g_plen2)[k];
    for (int i = tot + t; i < plen; i += 256) {
        pin[start + i] = (mode == 1) ? kZROW : kM;
        pout[start + i] = -1;
    }
}

// ---------------- tensor-core tap GEMM: M=64 x N=128 tiles -------------------
// 256 threads, 8 warps as 2(m)x4(n); warp tile 32x32. Static smem ~34KB,
// __launch_bounds__(256,2) -> 2 CTAs/SM. Depth-2 register prefetch,
// ldmatrix.x4 fragments, single-pass smem-transposed red.v4 scatter.
template <int MODE>
__global__ void __launch_bounds__(256, 2)
tapgemm_mma(float* __restrict__ ext_out)
{
    constexpr int CIN = (MODE == 1) ? kC : kCO;
    constexpr int BK  = 32;
    constexpr int NCH = CIN / BK;
    constexpr int LDB = 80;

    // tiles: Ahi[0,5120) Alo[5120,10240) Bhi[10240,20480) Blo[20480,30720)
    // epilogue aliases as T: 64 x 132 floats = 33792 bytes
    __shared__ __align__(16) char smem_raw[33792];
    __shared__ int sIdx[64], sOut[64];
    float* T = (float*)smem_raw;

    const int k = blockIdx.x >> 8;
    const int s = blockIdx.x & 255;
    const int plen = (MODE == 1 ? g_plen1 : g_plen2)[k];
    if (s * 64 >= plen) return;
    const int base = (MODE == 1 ? g_start1 : g_start2)[k] + s * 64;

    const __nv_bfloat16* __restrict__ shi = (MODE == 1) ? g_hhi : g_h1hi;
    const __nv_bfloat16* __restrict__ slo = (MODE == 1) ? g_hlo : g_h1lo;
    const __nv_bfloat16* __restrict__ whi = (MODE == 1) ? g_w1hi : g_w2hi;
    const __nv_bfloat16* __restrict__ wlo = (MODE == 1) ? g_w1lo : g_w2lo;
    const int* __restrict__ pin  = (MODE == 1) ? g_in1  : g_in2;
    const int* __restrict__ pout = (MODE == 1) ? g_out1 : g_out2;
    float* __restrict__ dstbase  = (MODE == 1) ? g_h1acc : ext_out;

    const int t = threadIdx.x;
    if (t < 64) {
        sIdx[t] = pin[base + t];
        sOut[t] = pout[base + t];
    }
    __syncthreads();

    const unsigned uB = smem_u32(smem_raw);
    const unsigned uAhi = uB, uAlo = uB + 5120;
    const unsigned uBhi = uB + 10240, uBlo = uB + 20480;

    const int warp = t >> 5, lane = t & 31;
    const int g = lane >> 2, tid = lane & 3;
    const int wm = (warp & 1) * 32;     // m offset (0/32)
    const int wn = (warp >> 1) * 32;    // n offset (0/32/64/96)

    const int a_row  = lane & 15;
    const int a_koff = (lane >> 4) * 16;
    const int b_row  = (lane & 7) + (lane >> 4) * 8;
    const int b_koff = ((lane >> 3) & 1) * 16;

    float acc[2][4][4];
    #pragma unroll
    for (int i = 0; i < 2; ++i)
        #pragma unroll
        for (int j = 0; j < 4; ++j)
            #pragma unroll
            for (int q = 0; q < 4; ++q) acc[i][j][q] = 0.f;

    const size_t wko = (size_t)k * 128 * CIN;

    const int r0 = t >> 2, j0 = t & 3;   // A row 0..63 / B rows r0, 64+r0
    const size_t aB  = (size_t)sIdx[r0] * CIN;
    const size_t b0b = wko + (size_t)r0 * CIN;
    const size_t b1b = wko + (size_t)(64 + r0) * CIN;
    const int toA  = r0 * LDB + j0 * 16;
    const int toB0 = r0 * LDB + j0 * 16;
    const int toB1 = (64 + r0) * LDB + j0 * 16 - 64 * LDB + 64 * LDB; // = toB0+64*LDB
    // (kept literal below for clarity)

    // depth-2 register prefetch: P[slot][0..5] = Ahi,Alo,BhiR0,BloR0,BhiR1,BloR1
    uint4 P[2][6];
    #pragma unroll
    for (int sl = 0; sl < 2 && sl < NCH; ++sl) {
        const int c0 = sl * BK;
        P[sl][0] = *((const uint4*)(shi + aB  + c0) + j0);
        P[sl][1] = *((const uint4*)(slo + aB  + c0) + j0);
        P[sl][2] = *((const uint4*)(whi + b0b + c0) + j0);
        P[sl][3] = *((const uint4*)(wlo + b0b + c0) + j0);
        P[sl][4] = *((const uint4*)(whi + b1b + c0) + j0);
        P[sl][5] = *((const uint4*)(wlo + b1b + c0) + j0);
    }

    #pragma unroll
    for (int ch = 0; ch < NCH; ++ch) {
        const int sl = ch & 1;
        *(uint4*)(smem_raw + toA)                       = P[sl][0];
        *(uint4*)(smem_raw + 5120 + toA)                = P[sl][1];
        *(uint4*)(smem_raw + 10240 + toB0)              = P[sl][2];
        *(uint4*)(smem_raw + 20480 + toB0)              = P[sl][3];
        *(uint4*)(smem_raw + 10240 + toB0 + 64 * LDB)   = P[sl][4];
        *(uint4*)(smem_raw + 20480 + toB0 + 64 * LDB)   = P[sl][5];
        __syncthreads();

        if (ch + 2 < NCH) {
            const int c0 = (ch + 2) * BK;
            P[sl][0] = *((const uint4*)(shi + aB  + c0) + j0);
            P[sl][1] = *((const uint4*)(slo + aB  + c0) + j0);
            P[sl][2] = *((const uint4*)(whi + b0b + c0) + j0);
            P[sl][3] = *((const uint4*)(wlo + b0b + c0) + j0);
            P[sl][4] = *((const uint4*)(whi + b1b + c0) + j0);
            P[sl][5] = *((const uint4*)(wlo + b1b + c0) + j0);
        }

        #pragma unroll
        for (int ks = 0; ks < BK / 16; ++ks) {
            const int akb = ks * 32 + a_koff;
            const int bkb = ks * 32 + b_koff;
            unsigned ah[2][4], al[2][4];
            #pragma unroll
            for (int mt = 0; mt < 2; ++mt) {
                unsigned aoff = (unsigned)((wm + mt * 16 + a_row) * LDB + akb);
                ldsm4(ah[mt], uAhi + aoff);
                ldsm4(al[mt], uAlo + aoff);
            }
            #pragma unroll
            for (int n2 = 0; n2 < 2; ++n2) {
                unsigned boff = (unsigned)((wn + n2 * 16 + b_row) * LDB + bkb);
                unsigned bh[4], bl[4];
                ldsm4(bh, uBhi + boff);
                ldsm4(bl, uBlo + boff);
                #pragma unroll
                for (int mt = 0; mt < 2; ++mt) {
                    mma16816(acc[mt][n2 * 2],     ah[mt], bh);
                    mma16816(acc[mt][n2 * 2],     ah[mt], bl);
                    mma16816(acc[mt][n2 * 2],     al[mt], bh);
                    mma16816(acc[mt][n2 * 2 + 1], ah[mt], bh + 2);
                    mma16816(acc[mt][n2 * 2 + 1], ah[mt], bl + 2);
                    mma16816(acc[mt][n2 * 2 + 1], al[mt], bh + 2);
                }
            }
        }
        __syncthreads();
    }

    // ---- epilogue: single-pass smem transpose -> coalesced red.v4 scatter ----
    const int cq = tid * 2;
    #pragma unroll
    for (int mt = 0; mt < 2; ++mt)
        #pragma unroll
        for (int half = 0; half < 2; ++half) {
            int lrow = wm + mt * 16 + g + half * 8;      // 0..63
            #pragma unroll
            for (int na = 0; na < 4; ++na) {
                int col = wn + na * 8 + cq;
                *(float2*)&T[lrow * 132 + col] =
                    make_float2(acc[mt][na][half * 2],
                                acc[mt][na][half * 2 + 1]);
            }
        }
    __syncthreads();
    #pragma unroll
    for (int i = 0; i < 8; ++i) {
        int lrow = warp * 8 + i;
        int orow = sOut[lrow];
        if (orow >= 0) {
            float4 v = *(const float4*)&T[lrow * 132 + lane * 4];
            red_v4(dstbase + (size_t)orow * kCO + lane * 4, v);
        }
    }
}

// ---------------- h1 epilogue: 2 rows per 256-thread block -------------------
__global__ void h1_ep_kernel(const float* __restrict__ c1b) {
    const int t = threadIdx.x;
    const int r = t >> 7;
    const int m = blockIdx.x * 2 + r;
    const int ct = t & 127;
    const int wid = (t >> 5) & 3, lane = t & 31;
    __shared__ float red[2][4];
    float x = g_h1acc[(size_t)m * kCO + ct] + c1b[ct];
    float s = x;
    #pragma unroll
    for (int o = 16; o; o >>= 1) s += __shfl_xor_sync(0xffffffffu, s, o);
    if (lane == 0) red[r][wid] = s;
    __syncthreads();
    const float mean = (red[r][0] + red[r][1] + red[r][2] + red[r][3]) * (1.f / kCO);
    const float d = x - mean;
    float s2 = d * d;
    #pragma unroll
    for (int o = 16; o; o >>= 1) s2 += __shfl_xor_sync(0xffffffffu, s2, o);
    __syncthreads();
    if (lane == 0) red[r][wid] = s2;
    __syncthreads();
    const float var = (red[r][0] + red[r][1] + red[r][2] + red[r][3]) * (1.f / kCO);
    const float y = d * rsqrtf(var + 1e-6f);
    const float h = y / (1.f + expf(-y));
    __nv_bfloat16 hh = __float2bfloat16(h);
    g_h1hi[(size_t)m * kCO + ct] = hh;
    g_h1lo[(size_t)m * kCO + ct] = __float2bfloat16(h - __bfloat162float(hh));
}

// ---------------- out epilogue: += c2 bias + skip acc + skip bias ------------
__global__ void out_ep_kernel(float* __restrict__ out,
                              const float* __restrict__ c2b,
                              const float* __restrict__ skb) {
    if ((int)blockIdx.x >= g_cnt) return;
    const int m = g_list[blockIdx.x], t = threadIdx.x;   // 128
    out[(size_t)m * kCO + t] +=
        c2b[t] + skb[t] + g_h1acc[(size_t)(kM + (m >> 3)) * kCO + t];
}

// ---------------- launch (ONLY harness pointers cross the boundary) ----------
extern "C" void kernel_launch(void* const* d_in, const int* in_sizes, int n_in,
                              void* d_out, int out_size)
{
    const float* feats = (const float*)d_in[0];
    const float* n1w   = (const float*)d_in[1];
    const float* n1b   = (const float*)d_in[2];
    const float* sdw   = (const float*)d_in[3];
    const float* sdb   = (const float*)d_in[4];
    const float* c1w   = (const float*)d_in[5];
    const float* c1b   = (const float*)d_in[6];
    const float* c2w   = (const float*)d_in[7];
    const float* c2b   = (const float*)d_in[8];
    const float* skw   = (const float*)d_in[9];
    const float* skb   = (const float*)d_in[10];
    const int*   coords= (const int*)d_in[11];

    float* out        = (float*)d_out;
    float* subdiv_out = out + (size_t)kM * kCO;

    prep_kernel<<<PREP_BLOCKS, 256>>>(out, c1w, c2w, skw);
    scatter_kernel<<<kM / 256, 256>>>(coords);        // MUST follow sentinel fill
    row_kernel<<<kN, 256>>>(feats, n1w, n1b, sdw, sdb, subdiv_out);
    nidx_kernel<<<dim3(kM / 256, 9), 256>>>(coords);
    tap_scan_kernel<<<1, 32>>>();
    tap_fill_kernel<<<55, 256>>>();
    tapgemm_mma<1><<<28 * 256, 256>>>(nullptr);       // conv1 taps + skip GEMM
    h1_ep_kernel<<<kM / 2, 256>>>(c1b);
    tapgemm_mma<2><<<27 * 256, 256>>>(out);
    out_ep_kernel<<<kM, 128>>>(out, c2b, skb);
}

// round 17
// speedup vs baseline: 1.0311x; 1.0233x over previous
#include <cuda_runtime.h>
#include <cuda_bf16.h>
#include <math.h>

// ---------------- problem constants ----------------
constexpr int kN  = 2048;
constexpr int kC  = 256;
constexpr int kCO = 128;
constexpr int kM  = 8 * kN;      // 16384
constexpr int kG  = 66;
constexpr int kG3 = kG * kG * kG;
constexpr int kZROW = 2 * kN;    // zero-pad row index in g_hhi/g_hlo

// ---------------- scratch globals (NEVER passed as kernel args from host) ----
__device__ __nv_bfloat16 g_hhi [(2 * kN + 1) * kC];
__device__ __nv_bfloat16 g_hlo [(2 * kN + 1) * kC];
__device__ __nv_bfloat16 g_h1hi[(kM + 1) * kCO];
__device__ __nv_bfloat16 g_h1lo[(kM + 1) * kCO];
__device__ float g_h1acc[(kM + kN) * kCO];   // [kM,kM+kN) = skip accumulator
__device__ int   g_grid[kG3];
__device__ int   g_nidx [kM * 27];
__device__ int   g_nidx1[kM * 27];
__device__ int   g_mask[kM];
__device__ int   g_cnt;
__device__ int   g_list[kM];
__device__ int   g_in1 [kM * 27 + 28 * 128 + 2048], g_out1[kM * 27 + 28 * 128 + 2048];
__device__ int   g_in2 [kM * 27 + 27 * 128], g_out2[kM * 27 + 27 * 128];
__device__ int   g_cnt1[28], g_start1[28], g_plen1[28];
__device__ int   g_cnt2[27], g_start2[27], g_plen2[27];
__device__ __nv_bfloat16 g_w1hi[28 * 128 * kC],  g_w1lo[28 * 128 * kC];
__device__ __nv_bfloat16 g_w2hi[27 * 128 * kCO], g_w2lo[27 * 128 * kCO];

// ---------------- ptx helpers ----------------
__device__ __forceinline__ unsigned smem_u32(const void* p) {
    unsigned a;
    asm("{ .reg .u64 t; cvta.to.shared.u64 t, %1; cvt.u32.u64 %0, t; }"
        : "=r"(a) : "l"(p));
    return a;
}
__device__ __forceinline__ void ldsm4(unsigned* r, unsigned addr) {
    asm volatile("ldmatrix.sync.aligned.m8n8.x4.shared.b16 {%0,%1,%2,%3}, [%4];"
                 : "=r"(r[0]), "=r"(r[1]), "=r"(r[2]), "=r"(r[3]) : "r"(addr));
}
__device__ __forceinline__ void mma16816(float* d, const unsigned* a,
                                         const unsigned* b) {
    asm volatile(
        "mma.sync.aligned.m16n8k16.row.col.f32.bf16.bf16.f32 "
        "{%0,%1,%2,%3}, {%4,%5,%6,%7}, {%8,%9}, {%0,%1,%2,%3};"
        : "+f"(d[0]), "+f"(d[1]), "+f"(d[2]), "+f"(d[3])
        : "r"(a[0]), "r"(a[1]), "r"(a[2]), "r"(a[3]), "r"(b[0]), "r"(b[1]));
}
__device__ __forceinline__ void red_v4(float* p, float4 v) {
    asm volatile("red.global.add.v4.f32 [%0], {%1, %2, %3, %4};"
                 :: "l"(p), "f"(v.x), "f"(v.y), "f"(v.z), "f"(v.w) : "memory");
}

// ---------------- fused prep (float4 zeroing; child scatter lives in row) ----
constexpr int PB0 = (kM * kCO) / 1024;         // 2048  zero h1acc[0,kM)+out (f4)
constexpr int PBS = (kN * kCO) / 1024;         // 256   zero skip acc (f4)
constexpr int PT1 = 27 * 8 * 4;                // 864
constexpr int PTS = 8 * 4;                     // 32
constexpr int PT2 = 27 * 4 * 4;                // 432
constexpr int PB3 = (kG3 + 255) / 256;         // 1124  grid sentinel
constexpr int PREP_BLOCKS = PB0 + PBS + PT1 + PTS + PT2 + PB3 + 1;

__global__ void prep_kernel(float* __restrict__ out,
                            const float* __restrict__ c1w,
                            const float* __restrict__ c2w,
                            const float* __restrict__ skw) {
    __shared__ float sT[32][33];
    const int b = blockIdx.x, t = threadIdx.x;
    const float4 z4 = make_float4(0.f, 0.f, 0.f, 0.f);
    if (b < PB0) {
        int i = b * 256 + t;
        ((float4*)g_h1acc)[i] = z4;
        ((float4*)out)[i] = z4;
    } else if (b < PB0 + PBS) {
        ((float4*)(g_h1acc + kM * kCO))[(b - PB0) * 256 + t] = z4;
    } else if (b < PB0 + PBS + PT1 + PTS) {
        int b1 = b - PB0 - PBS;
        int k = b1 >> 5, r = b1 & 31;
        int c0 = (r >> 2) * 32, n0 = (r & 3) * 32;
        const float* wk = (k < 27) ? (c1w + (size_t)k * kC * 128) : skw;
        int nx = t & 31, cy = t >> 5;
        #pragma unroll
        for (int i = 0; i < 4; ++i)
            sT[cy + 8 * i][nx] = wk[(size_t)(c0 + cy + 8 * i) * 128 + n0 + nx];
        __syncthreads();
        int cx = t & 31, ny = t >> 5;
        #pragma unroll
        for (int i = 0; i < 4; ++i) {
            float v = sT[cx][ny + 8 * i];
            __nv_bfloat16 h = __float2bfloat16(v);
            size_t o = (size_t)k * 128 * kC + (size_t)(n0 + ny + 8 * i) * kC + c0 + cx;
            g_w1hi[o] = h;
            g_w1lo[o] = __float2bfloat16(v - __bfloat162float(h));
        }
    } else if (b < PB0 + PBS + PT1 + PTS + PT2) {
        int b2 = b - PB0 - PBS - PT1 - PTS;
        int k = b2 >> 4, r = b2 & 15;
        int c0 = (r >> 2) * 32, n0 = (r & 3) * 32;
        const float* wk = c2w + (size_t)k * kCO * 128;
        int nx = t & 31, cy = t >> 5;
        #pragma unroll
        for (int i = 0; i < 4; ++i)
            sT[cy + 8 * i][nx] = wk[(size_t)(c0 + cy + 8 * i) * 128 + n0 + nx];
        __syncthreads();
        int cx = t & 31, ny = t >> 5;
        #pragma unroll
        for (int i = 0; i < 4; ++i) {
            float v = sT[cx][ny + 8 * i];
            __nv_bfloat16 h = __float2bfloat16(v);
            size_t o = (size_t)k * 128 * kCO + (size_t)(n0 + ny + 8 * i) * kCO + c0 + cx;
            g_w2hi[o] = h;
            g_w2lo[o] = __float2bfloat16(v - __bfloat162float(h));
        }
    } else if (b < PB0 + PBS + PT1 + PTS + PT2 + PB3) {
        int i = (b - PB0 - PBS - PT1 - PTS - PT2) * 256 + t;
        if (i < kG3) g_grid[i] = kM;
    } else {
        if (t < kC)  { g_hhi[(size_t)kZROW * kC + t] = __float2bfloat16(0.f);
                       g_hlo[(size_t)kZROW * kC + t] = __float2bfloat16(0.f); }
        if (t < kCO) { g_h1hi[kM * kCO + t] = __float2bfloat16(0.f);
                       g_h1lo[kM * kCO + t] = __float2bfloat16(0.f); }
        if (t == 0)  g_cnt = 0;
        if (t < 28)  { g_cnt1[t] = 0; if (t < 27) g_cnt2[t] = 0; }
    }
}

// ---------------- per-parent: subdiv + mask + compact + LN + SiLU + scatter --
// (grid scatter fused here; prep's sentinel fill is in the PREVIOUS launch)
__global__ void row_kernel(const float* __restrict__ feats,
                           const float* __restrict__ n1w,
                           const float* __restrict__ n1b,
                           const float* __restrict__ sdw,
                           const float* __restrict__ sdb,
                           float* __restrict__ subdiv_out,
                           const int* __restrict__ coords) {
    const int n = blockIdx.x;
    const int t = threadIdx.x;           // 256
    const int wid = t >> 5, lane = t & 31;
    __shared__ float sf[kC];
    __shared__ float red[8];
    __shared__ int   s_act[8];

    // scatter this parent's 8 children into the grid (threads 0..7)
    if (t < 8) {
        int cx = coords[n * 3 + 0] * 2 + ((t >> 2) & 1);
        int cy = coords[n * 3 + 1] * 2 + ((t >> 1) & 1);
        int cz = coords[n * 3 + 2] * 2 + (t & 1);
        g_grid[((cx + 1) * kG + (cy + 1)) * kG + (cz + 1)] = n * 8 + t;
    }

    float x = feats[n * kC + t];
    sf[t] = x;
    {
        __nv_bfloat16 fh = __float2bfloat16(x);
        g_hhi[(size_t)(kN + n) * kC + t] = fh;
        g_hlo[(size_t)(kN + n) * kC + t] =
            __float2bfloat16(x - __bfloat162float(fh));
    }
    __syncthreads();

    {
        float p = 0.f;
        #pragma unroll
        for (int i = 0; i < 8; ++i) {
            int c = lane + i * 32;
            p += sf[c] * sdw[c * 8 + wid];
        }
        #pragma unroll
        for (int o = 16; o; o >>= 1) p += __shfl_xor_sync(0xffffffffu, p, o);
        if (lane == 0) {
            p += sdb[wid];
            subdiv_out[n * 8 + wid] = p;
            int act = (p > 0.f) ? 1 : 0;
            g_mask[n * 8 + wid] = act;
            s_act[wid] = act;
        }
    }

    float s = x;
    #pragma unroll
    for (int o = 16; o; o >>= 1) s += __shfl_xor_sync(0xffffffffu, s, o);
    if (lane == 0) red[wid] = s;
    __syncthreads();

    if (wid == 0) {
        bool act = (lane < 8) && (s_act[lane] != 0);
        unsigned ball = __ballot_sync(0xffffffffu, act);
        int c = __popc(ball);
        int base = 0;
        if (lane == 0 && c) base = atomicAdd(&g_cnt, c);
        base = __shfl_sync(0xffffffffu, base, 0);
        if (act) g_list[base + __popc(ball & ((1u << lane) - 1u))] = n * 8 + lane;
    }

    float tot = 0.f;
    #pragma unroll
    for (int i = 0; i < 8; ++i) tot += red[i];
    const float mean = tot * (1.f / kC);
    const float d = x - mean;
    float s2 = d * d;
    #pragma unroll
    for (int o = 16; o; o >>= 1) s2 += __shfl_xor_sync(0xffffffffu, s2, o);
    __syncthreads();
    if (lane == 0) red[wid] = s2;
    __syncthreads();
    float vtot = 0.f;
    #pragma unroll
    for (int i = 0; i < 8; ++i) vtot += red[i];
    const float var = vtot * (1.f / kC);
    const float y = d * rsqrtf(var + 1e-6f) * n1w[t] + n1b[t];
    const float h = y / (1.f + expf(-y));
    __nv_bfloat16 hh = __float2bfloat16(h);
    g_hhi[(size_t)n * kC + t] = hh;
    g_hlo[(size_t)n * kC + t] = __float2bfloat16(h - __bfloat162float(hh));
}

// ---------------- neighbor table + tap counting (64 x 9 blocks, 3 taps) ------
__global__ void nidx_kernel(const int* __restrict__ coords) {
    __shared__ int c1[3], c2[3];
    const int t = threadIdx.x;
    const int lane = t & 31;
    const int k0 = blockIdx.y * 3;
    if (t < 3) { c1[t] = 0; c2[t] = 0; }
    __syncthreads();

    int m = blockIdx.x * 256 + t;
    int n = m >> 3, j = m & 7;
    int gx = coords[n * 3 + 0] * 2 + ((j >> 2) & 1) + 1;
    int gy = coords[n * 3 + 1] * 2 + ((j >> 1) & 1) + 1;
    int gz = coords[n * 3 + 2] * 2 + (j & 1) + 1;
    const int msk = g_mask[m];
    #pragma unroll
    for (int kk = 0; kk < 3; ++kk) {
        int k = k0 + kk;
        int dx = k / 9 - 1, dy = (k / 3) % 3 - 1, dz = k % 3 - 1;
        int nb = g_grid[((gx + dx) * kG + (gy + dy)) * kG + (gz + dz)];
        g_nidx[m * 27 + k] = nb;
        int in1 = (nb == kM) ? kZROW : (g_mask[nb] ? (nb >> 3) : kZROW);
        g_nidx1[m * 27 + k] = in1;
        unsigned b1 = __ballot_sync(0xffffffffu, in1 != kZROW);
        unsigned b2 = __ballot_sync(0xffffffffu, msk && (nb != kM));
        if (lane == 0) {
            if (b1) atomicAdd(&c1[kk], __popc(b1));
            if (b2) atomicAdd(&c2[kk], __popc(b2));
        }
    }
    __syncthreads();
    if (t < 3) {
        if (c1[t]) atomicAdd(&g_cnt1[k0 + t], c1[t]);
        if (c2[t]) atomicAdd(&g_cnt2[k0 + t], c2[t]);
    }
}

// ---------------- fill pair lists (55 blocks) + inline scan ------------------
// Each block derives its segment start from g_cnt arrays (27 loads, cheap at
// 55 blocks) and publishes g_start/g_plen for the tapgemm launches.
__device__ __forceinline__ bool tap_flag_rt(int mode, int m, int k, int& in_id) {
    if (mode == 1) {
        in_id = g_nidx1[m * 27 + k];
        return in_id != kZROW;
    } else {
        in_id = g_nidx[m * 27 + k];
        return g_mask[m] && (in_id != kM);
    }
}

__global__ void tap_fill_kernel() {
    const int mode = (blockIdx.x < 28) ? 1 : 2;
    const int k = (mode == 1) ? blockIdx.x : (blockIdx.x - 28);
    const int t = threadIdx.x;
    int* __restrict__ pin  = (mode == 1) ? g_in1  : g_in2;
    int* __restrict__ pout = (mode == 1) ? g_out1 : g_out2;
    const int* __restrict__ cnts = (mode == 1) ? g_cnt1 : g_cnt2;

    __shared__ int s_start;
    if (t == 0) {
        int s = 0;
        for (int i = 0; i < k && i < 27; ++i) s += (cnts[i] + 127) & ~127;
        int plen = (k == 27) ? kN : ((cnts[k] + 127) & ~127);
        s_start = s;
        if (mode == 1) { g_start1[k] = s; g_plen1[k] = plen; }
        else           { g_start2[k] = s; g_plen2[k] = plen; }
    }
    __syncthreads();
    const int start = s_start;

    if (mode == 1 && k == 27) {
        for (int i = t; i < kN; i += 256) {
            pin[start + i] = kN + i;
            pout[start + i] = kM + i;
        }
        return;
    }

    int cnt = 0;
    #pragma unroll 4
    for (int r = 0; r < 64; ++r) {
        int in_id;
        if (tap_flag_rt(mode, t * 64 + r, k, in_id)) ++cnt;
    }
    __shared__ int sh[256];
    sh[t] = cnt;
    __syncthreads();
    #pragma unroll
    for (int off = 1; off < 256; off <<= 1) {
        int u = (t >= off) ? sh[t - off] : 0;
        __syncthreads();
        sh[t] += u;
        __syncthreads();
    }
    int w = start + sh[t] - cnt;
    const int tot = sh[255];
    for (int r = 0; r < 64; ++r) {
        int m = t * 64 + r, in_id;
        if (tap_flag_rt(mode, m, k, in_id)) {
            pin[w] = in_id;
            pout[w] = m;
            ++w;
        }
    }
    const int plen = (cnts[k] + 127) & ~127;
    for (int i = tot + t; i < plen; i += 256) {
        pin[start + i] = (mode == 1) ? kZROW : kM;
        pout[start + i] = -1;
    }
}

// ---------------- tensor-core tap GEMM: M=64 x N=128 tiles -------------------
// 256 threads, 8 warps as 2(m)x4(n); warp tile 32x32. Static smem ~34KB,
// __launch_bounds__(256,2) -> 2 CTAs/SM. Depth-2 register prefetch,
// ldmatrix.x4 fragments, single-pass smem-transposed red.v4 scatter.
template <int MODE>
__global__ void __launch_bounds__(256, 2)
tapgemm_mma(float* __restrict__ ext_out)
{
    constexpr int CIN = (MODE == 1) ? kC : kCO;
    constexpr int BK  = 32;
    constexpr int NCH = CIN / BK;
    constexpr int LDB = 80;

    __shared__ __align__(16) char smem_raw[33792];
    __shared__ int sIdx[64], sOut[64];
    float* T = (float*)smem_raw;

    const int k = blockIdx.x >> 8;
    const int s = blockIdx.x & 255;
    const int plen = (MODE == 1 ? g_plen1 : g_plen2)[k];
    if (s * 64 >= plen) return;
    const int base = (MODE == 1 ? g_start1 : g_start2)[k] + s * 64;

    const __nv_bfloat16* __restrict__ shi = (MODE == 1) ? g_hhi : g_h1hi;
    const __nv_bfloat16* __restrict__ slo = (MODE == 1) ? g_hlo : g_h1lo;
    const __nv_bfloat16* __restrict__ whi = (MODE == 1) ? g_w1hi : g_w2hi;
    const __nv_bfloat16* __restrict__ wlo = (MODE == 1) ? g_w1lo : g_w2lo;
    const int* __restrict__ pin  = (MODE == 1) ? g_in1  : g_in2;
    const int* __restrict__ pout = (MODE == 1) ? g_out1 : g_out2;
    float* __restrict__ dstbase  = (MODE == 1) ? g_h1acc : ext_out;

    const int t = threadIdx.x;
    if (t < 64) {
        sIdx[t] = pin[base + t];
        sOut[t] = pout[base + t];
    }
    __syncthreads();

    const unsigned uB = smem_u32(smem_raw);
    const unsigned uAhi = uB, uAlo = uB + 5120;
    const unsigned uBhi = uB + 10240, uBlo = uB + 20480;

    const int warp = t >> 5, lane = t & 31;
    const int g = lane >> 2, tid = lane & 3;
    const int wm = (warp & 1) * 32;
    const int wn = (warp >> 1) * 32;

    const int a_row  = lane & 15;
    const int a_koff = (lane >> 4) * 16;
    const int b_row  = (lane & 7) + (lane >> 4) * 8;
    const int b_koff = ((lane >> 3) & 1) * 16;

    float acc[2][4][4];
    #pragma unroll
    for (int i = 0; i < 2; ++i)
        #pragma unroll
        for (int j = 0; j < 4; ++j)
            #pragma unroll
            for (int q = 0; q < 4; ++q) acc[i][j][q] = 0.f;

    const size_t wko = (size_t)k * 128 * CIN;

    const int r0 = t >> 2, j0 = t & 3;
    const size_t aB  = (size_t)sIdx[r0] * CIN;
    const size_t b0b = wko + (size_t)r0 * CIN;
    const size_t b1b = wko + (size_t)(64 + r0) * CIN;
    const int toA  = r0 * LDB + j0 * 16;
    const int toB0 = r0 * LDB + j0 * 16;

    uint4 P[2][6];
    #pragma unroll
    for (int sl = 0; sl < 2 && sl < NCH; ++sl) {
        const int c0 = sl * BK;
        P[sl][0] = *((const uint4*)(shi + aB  + c0) + j0);
        P[sl][1] = *((const uint4*)(slo + aB  + c0) + j0);
        P[sl][2] = *((const uint4*)(whi + b0b + c0) + j0);
        P[sl][3] = *((const uint4*)(wlo + b0b + c0) + j0);
        P[sl][4] = *((const uint4*)(whi + b1b + c0) + j0);
        P[sl][5] = *((const uint4*)(wlo + b1b + c0) + j0);
    }

    #pragma unroll
    for (int ch = 0; ch < NCH; ++ch) {
        const int sl = ch & 1;
        *(uint4*)(smem_raw + toA)                       = P[sl][0];
        *(uint4*)(smem_raw + 5120 + toA)                = P[sl][1];
        *(uint4*)(smem_raw + 10240 + toB0)              = P[sl][2];
        *(uint4*)(smem_raw + 20480 + toB0)              = P[sl][3];
        *(uint4*)(smem_raw + 10240 + toB0 + 64 * LDB)   = P[sl][4];
        *(uint4*)(smem_raw + 20480 + toB0 + 64 * LDB)   = P[sl][5];
        __syncthreads();

        if (ch + 2 < NCH) {
            const int c0 = (ch + 2) * BK;
            P[sl][0] = *((const uint4*)(shi + aB  + c0) + j0);
            P[sl][1] = *((const uint4*)(slo + aB  + c0) + j0);
            P[sl][2] = *((const uint4*)(whi + b0b + c0) + j0);
            P[sl][3] = *((const uint4*)(wlo + b0b + c0) + j0);
            P[sl][4] = *((const uint4*)(whi + b1b + c0) + j0);
            P[sl][5] = *((const uint4*)(wlo + b1b + c0) + j0);
        }

        #pragma unroll
        for (int ks = 0; ks < BK / 16; ++ks) {
            const int akb = ks * 32 + a_koff;
            const int bkb = ks * 32 + b_koff;
            unsigned ah[2][4], al[2][4];
            #pragma unroll
            for (int mt = 0; mt < 2; ++mt) {
                unsigned aoff = (unsigned)((wm + mt * 16 + a_row) * LDB + akb);
                ldsm4(ah[mt], uAhi + aoff);
                ldsm4(al[mt], uAlo + aoff);
            }
            #pragma unroll
            for (int n2 = 0; n2 < 2; ++n2) {
                unsigned boff = (unsigned)((wn + n2 * 16 + b_row) * LDB + bkb);
                unsigned bh[4], bl[4];
                ldsm4(bh, uBhi + boff);
                ldsm4(bl, uBlo + boff);
                #pragma unroll
                for (int mt = 0; mt < 2; ++mt) {
                    mma16816(acc[mt][n2 * 2],     ah[mt], bh);
                    mma16816(acc[mt][n2 * 2],     ah[mt], bl);
                    mma16816(acc[mt][n2 * 2],     al[mt], bh);
                    mma16816(acc[mt][n2 * 2 + 1], ah[mt], bh + 2);
                    mma16816(acc[mt][n2 * 2 + 1], ah[mt], bl + 2);
                    mma16816(acc[mt][n2 * 2 + 1], al[mt], bh + 2);
                }
            }
        }
        __syncthreads();
    }

    // ---- epilogue: single-pass smem transpose -> coalesced red.v4 scatter ----
    const int cq = tid * 2;
    #pragma unroll
    for (int mt = 0; mt < 2; ++mt)
        #pragma unroll
        for (int half = 0; half < 2; ++half) {
            int lrow = wm + mt * 16 + g + half * 8;
            #pragma unroll
            for (int na = 0; na < 4; ++na) {
                int col = wn + na * 8 + cq;
                *(float2*)&T[lrow * 132 + col] =
                    make_float2(acc[mt][na][half * 2],
                                acc[mt][na][half * 2 + 1]);
            }
        }
    __syncthreads();
    #pragma unroll
    for (int i = 0; i < 8; ++i) {
        int lrow = warp * 8 + i;
        int orow = sOut[lrow];
        if (orow >= 0) {
            float4 v = *(const float4*)&T[lrow * 132 + lane * 4];
            red_v4(dstbase + (size_t)orow * kCO + lane * 4, v);
        }
    }
}

// ---------------- h1 epilogue: 2 rows per 256-thread block -------------------
__global__ void h1_ep_kernel(const float* __restrict__ c1b) {
    const int t = threadIdx.x;
    const int r = t >> 7;
    const int m = blockIdx.x * 2 + r;
    const int ct = t & 127;
    const int wid = (t >> 5) & 3, lane = t & 31;
    __shared__ float red[2][4];
    float x = g_h1acc[(size_t)m * kCO + ct] + c1b[ct];
    float s = x;
    #pragma unroll
    for (int o = 16; o; o >>= 1) s += __shfl_xor_sync(0xffffffffu, s, o);
    if (lane == 0) red[r][wid] = s;
    __syncthreads();
    const float mean = (red[r][0] + red[r][1] + red[r][2] + red[r][3]) * (1.f / kCO);
    const float d = x - mean;
    float s2 = d * d;
    #pragma unroll
    for (int o = 16; o; o >>= 1) s2 += __shfl_xor_sync(0xffffffffu, s2, o);
    __syncthreads();
    if (lane == 0) red[r][wid] = s2;
    __syncthreads();
    const float var = (red[r][0] + red[r][1] + red[r][2] + red[r][3]) * (1.f / kCO);
    const float y = d * rsqrtf(var + 1e-6f);
    const float h = y / (1.f + expf(-y));
    __nv_bfloat16 hh = __float2bfloat16(h);
    g_h1hi[(size_t)m * kCO + ct] = hh;
    g_h1lo[(size_t)m * kCO + ct] = __float2bfloat16(h - __bfloat162float(hh));
}

// ---------------- out epilogue: += c2 bias + skip acc + skip bias ------------
__global__ void out_ep_kernel(float* __restrict__ out,
                              const float* __restrict__ c2b,
                              const float* __restrict__ skb) {
    if ((int)blockIdx.x >= g_cnt) return;
    const int m = g_list[blockIdx.x], t = threadIdx.x;   // 128
    out[(size_t)m * kCO + t] +=
        c2b[t] + skb[t] + g_h1acc[(size_t)(kM + (m >> 3)) * kCO + t];
}

// ---------------- launch (ONLY harness pointers cross the boundary) ----------
extern "C" void kernel_launch(void* const* d_in, const int* in_sizes, int n_in,
                              void* d_out, int out_size)
{
    const float* feats = (const float*)d_in[0];
    const float* n1w   = (const float*)d_in[1];
    const float* n1b   = (const float*)d_in[2];
    const float* sdw   = (const float*)d_in[3];
    const float* sdb   = (const float*)d_in[4];
    const float* c1w   = (const float*)d_in[5];
    const float* c1b   = (const float*)d_in[6];
    const float* c2w   = (const float*)d_in[7];
    const float* c2b   = (const float*)d_in[8];
    const float* skw   = (const float*)d_in[9];
    const float* skb   = (const float*)d_in[10];
    const int*   coords= (const int*)d_in[11];

    float* out        = (float*)d_out;
    float* subdiv_out = out + (size_t)kM * kCO;

    prep_kernel<<<PREP_BLOCKS, 256>>>(out, c1w, c2w, skw);
    row_kernel<<<kN, 256>>>(feats, n1w, n1b, sdw, sdb, subdiv_out, coords);
    nidx_kernel<<<dim3(kM / 256, 9), 256>>>(coords);
    tap_fill_kernel<<<55, 256>>>();
    tapgemm_mma<1><<<28 * 256, 256>>>(nullptr);       // conv1 taps + skip GEMM
    h1_ep_kernel<<<kM / 2, 256>>>(c1b);
    tapgemm_mma<2><<<27 * 256, 256>>>(out);
    out_ep_kernel<<<kM, 128>>>(out, c2b, skb);
}